// round 1
// baseline (speedup 1.0000x reference)
#include <cuda_runtime.h>
#include <math.h>

// Problem sizes (fixed)
#define BB 64     // batch
#define SS 512    // seq len
#define DD 512    // input dim
#define HH 512    // hidden

// ---------------------------------------------------------------------------
// Device scratch (allocation-free rule: device globals only)
// ---------------------------------------------------------------------------
__device__ float g_gi[(size_t)SS * BB * 3 * HH];   // [s][b][3H]  (~201 MB)
__device__ float g_f [(size_t)SS * BB * 2 * HH];   // [s][b][2H]  (~134 MB)
__device__ float g_h [2][BB * HH];                 // h ping-pong
__device__ unsigned g_bar[4];                      // per-batch-group barrier

__global__ void init_bar_kernel() {
    if (threadIdx.x < 4) g_bar[threadIdx.x] = 0u;
}

// ---------------------------------------------------------------------------
// SGEMM 1: gi[s][b][n] = input[b][s][:] . W_ih[n][:] + bias_ih[n]
// M = B*S = 32768 (m = b*512 + s), N = 1536, K = 512
// Tile 128x128, BK=32, 256 threads, 8x8 per-thread accumulators.
// ---------------------------------------------------------------------------
__global__ __launch_bounds__(256) void gemm_gi_kernel(
    const float* __restrict__ A, const float* __restrict__ W,
    const float* __restrict__ bias)
{
    __shared__ float As[32 * 128];   // [k][m]
    __shared__ float Bs[32 * 128];   // [k][n]
    const int t  = threadIdx.x;
    const int m0 = blockIdx.x * 128;
    const int n0 = blockIdx.y * 128;
    const int lr = t >> 3;           // 0..31
    const int lk = (t & 7) << 2;     // 0,4,...,28
    const int tx = t & 15, ty = t >> 4;

    float acc[8][8];
#pragma unroll
    for (int i = 0; i < 8; i++)
#pragma unroll
        for (int j = 0; j < 8; j++) acc[i][j] = 0.f;

    for (int k0 = 0; k0 < 512; k0 += 32) {
#pragma unroll
        for (int i = 0; i < 4; i++) {
            int row = lr + 32 * i;
            float4 v = *(const float4*)&A[(size_t)(m0 + row) * 512 + k0 + lk];
            As[(lk + 0) * 128 + row] = v.x;
            As[(lk + 1) * 128 + row] = v.y;
            As[(lk + 2) * 128 + row] = v.z;
            As[(lk + 3) * 128 + row] = v.w;
            float4 w = *(const float4*)&W[(size_t)(n0 + row) * 512 + k0 + lk];
            Bs[(lk + 0) * 128 + row] = w.x;
            Bs[(lk + 1) * 128 + row] = w.y;
            Bs[(lk + 2) * 128 + row] = w.z;
            Bs[(lk + 3) * 128 + row] = w.w;
        }
        __syncthreads();
#pragma unroll
        for (int k = 0; k < 32; k++) {
            float a[8], b[8];
            *(float4*)(a)     = *(const float4*)&As[k * 128 + (ty << 2)];
            *(float4*)(a + 4) = *(const float4*)&As[k * 128 + 64 + (ty << 2)];
            *(float4*)(b)     = *(const float4*)&Bs[k * 128 + (tx << 2)];
            *(float4*)(b + 4) = *(const float4*)&Bs[k * 128 + 64 + (tx << 2)];
#pragma unroll
            for (int i = 0; i < 8; i++)
#pragma unroll
                for (int j = 0; j < 8; j++) acc[i][j] += a[i] * b[j];
        }
        __syncthreads();
    }

#pragma unroll
    for (int i = 0; i < 8; i++) {
        int ml = (i < 4) ? ((ty << 2) + i) : (64 + (ty << 2) + i - 4);
        int m = m0 + ml;
        int b = m >> 9;          // m = b*512 + s
        int s = m & 511;
        float* crow = &g_gi[((size_t)s * 64 + b) * 1536];
#pragma unroll
        for (int jb = 0; jb < 2; jb++) {
            int n = n0 + jb * 64 + (tx << 2);
            float4 bv = *(const float4*)&bias[n];
            float4 r;
            r.x = acc[i][jb * 4 + 0] + bv.x;
            r.y = acc[i][jb * 4 + 1] + bv.y;
            r.z = acc[i][jb * 4 + 2] + bv.z;
            r.w = acc[i][jb * 4 + 3] + bv.w;
            *(float4*)&crow[n] = r;
        }
    }
}

// ---------------------------------------------------------------------------
// SGEMM 2: f[s][b][n] = 0.5 * sum_a ( aux[a][b][s][:] . W_fh[a][n][:] )
//                      + 0.5 * (bias_fh[0][n] + bias_fh[1][n])
// N = 1024, two K=512 accumulation passes (one per aux stream).
// ---------------------------------------------------------------------------
__global__ __launch_bounds__(256) void gemm_f_kernel(
    const float* __restrict__ Aux, const float* __restrict__ Wf,
    const float* __restrict__ bf)
{
    __shared__ float As[32 * 128];
    __shared__ float Bs[32 * 128];
    const int t  = threadIdx.x;
    const int m0 = blockIdx.x * 128;
    const int n0 = blockIdx.y * 128;
    const int lr = t >> 3;
    const int lk = (t & 7) << 2;
    const int tx = t & 15, ty = t >> 4;

    float acc[8][8];
#pragma unroll
    for (int i = 0; i < 8; i++)
#pragma unroll
        for (int j = 0; j < 8; j++) acc[i][j] = 0.f;

    for (int a = 0; a < 2; a++) {
        const float* A = Aux + (size_t)a * 32768 * 512;
        const float* W = Wf  + (size_t)a * 1024 * 512;
        for (int k0 = 0; k0 < 512; k0 += 32) {
#pragma unroll
            for (int i = 0; i < 4; i++) {
                int row = lr + 32 * i;
                float4 v = *(const float4*)&A[(size_t)(m0 + row) * 512 + k0 + lk];
                As[(lk + 0) * 128 + row] = v.x;
                As[(lk + 1) * 128 + row] = v.y;
                As[(lk + 2) * 128 + row] = v.z;
                As[(lk + 3) * 128 + row] = v.w;
                float4 w = *(const float4*)&W[(size_t)(n0 + row) * 512 + k0 + lk];
                Bs[(lk + 0) * 128 + row] = w.x;
                Bs[(lk + 1) * 128 + row] = w.y;
                Bs[(lk + 2) * 128 + row] = w.z;
                Bs[(lk + 3) * 128 + row] = w.w;
            }
            __syncthreads();
#pragma unroll
            for (int k = 0; k < 32; k++) {
                float av[8], bv[8];
                *(float4*)(av)     = *(const float4*)&As[k * 128 + (ty << 2)];
                *(float4*)(av + 4) = *(const float4*)&As[k * 128 + 64 + (ty << 2)];
                *(float4*)(bv)     = *(const float4*)&Bs[k * 128 + (tx << 2)];
                *(float4*)(bv + 4) = *(const float4*)&Bs[k * 128 + 64 + (tx << 2)];
#pragma unroll
                for (int i = 0; i < 8; i++)
#pragma unroll
                    for (int j = 0; j < 8; j++) acc[i][j] += av[i] * bv[j];
            }
            __syncthreads();
        }
    }

#pragma unroll
    for (int i = 0; i < 8; i++) {
        int ml = (i < 4) ? ((ty << 2) + i) : (64 + (ty << 2) + i - 4);
        int m = m0 + ml;
        int b = m >> 9;
        int s = m & 511;
        float* crow = &g_f[((size_t)s * 64 + b) * 1024];
#pragma unroll
        for (int jb = 0; jb < 2; jb++) {
            int n = n0 + jb * 64 + (tx << 2);
            float4 b0 = *(const float4*)&bf[n];
            float4 b1 = *(const float4*)&bf[1024 + n];
            float4 r;
            r.x = 0.5f * acc[i][jb * 4 + 0] + 0.5f * (b0.x + b1.x);
            r.y = 0.5f * acc[i][jb * 4 + 1] + 0.5f * (b0.y + b1.y);
            r.z = 0.5f * acc[i][jb * 4 + 2] + 0.5f * (b0.z + b1.z);
            r.w = 0.5f * acc[i][jb * 4 + 3] + 0.5f * (b0.w + b1.w);
            *(float4*)&crow[n] = r;
        }
    }
}

// ---------------------------------------------------------------------------
// Persistent recurrent scan.
// Grid = 128 CTAs = 4 batch-groups (16 b each) x 32 column-CTAs (16 hy-cols
// => 48 W_hh rows each). Each CTA holds its W_hh slice in smem for all 512
// steps. h is double-buffered in g_h; each step ends with a 32-CTA
// group-local atomic barrier. 1 CTA/SM (134 KB smem), grid <= #SMs =>
// all CTAs co-resident, barrier is deadlock-free.
// ---------------------------------------------------------------------------
#define HS_PITCH 516
#define SCAN_SMEM_FLOATS (48 * 512 + 16 * HS_PITCH + 48 * 16 + 48)
#define SCAN_SMEM_BYTES  (SCAN_SMEM_FLOATS * 4)

__global__ __launch_bounds__(256, 1) void scan_kernel(
    const float* __restrict__ hx, const float* __restrict__ Whh,
    const float* __restrict__ bias_hh, float* __restrict__ out)
{
    extern __shared__ float smem[];
    float* Ws  = smem;                     // [48][512]
    float* hs  = Ws + 48 * 512;            // [16][HS_PITCH]
    float* ghs = hs + 16 * HS_PITCH;       // [48][16]
    float* bs  = ghs + 48 * 16;            // [48]

    const int t   = threadIdx.x;
    const int gid = blockIdx.x >> 5;       // batch group 0..3
    const int cid = blockIdx.x & 31;       // column CTA 0..31
    const int b0  = gid * 16;
    const int c0  = cid * 16;

    // Load W_hh slice once: rows = {gate*512 + c0 + j : gate in 0..2, j in 0..15}
    for (int i = t; i < 48 * 128; i += 256) {
        int r  = i >> 7;                   // 0..47
        int c4 = i & 127;
        int gate = r >> 4, j = r & 15;
        int grow = gate * 512 + c0 + j;
        *(float4*)&Ws[r * 512 + c4 * 4] =
            *(const float4*)&Whh[(size_t)grow * 512 + c4 * 4];
    }
    if (t < 48) {
        int gate = t >> 4, j = t & 15;
        bs[t] = bias_hh[gate * 512 + c0 + j];
    }

    // dot-phase assignment: thread computes rows r0..r0+2 for batch db
    const int db = t & 15;
    const int rg = t >> 4;                 // 0..15
    const int r0 = rg * 3;
    // epilogue assignment: thread handles (batch eb, column ej)
    const int eb = t >> 4;
    const int ej = t & 15;
    const int bglob = b0 + eb;

    for (int s = 0; s < 512; s++) {
        // Stage h[b0..b0+15][0..511] into smem
        const float* hsrc = (s == 0) ? (hx + (size_t)b0 * 512)
                                     : (g_h[s & 1] + (size_t)b0 * 512);
        for (int i = t; i < 2048; i += 256) {   // 2048 float4 = 16*512 floats
            int bb = i >> 7;
            int c4 = i & 127;
            *(float4*)&hs[bb * HS_PITCH + c4 * 4] =
                *(const float4*)&hsrc[bb * 512 + c4 * 4];
        }

        // Prefetch gi / f operands (independent of h -> overlap with dots)
        size_t gib = ((size_t)s * 64 + bglob) * 1536 + c0 + ej;
        float i_r = g_gi[gib];
        float i_i = g_gi[gib + 512];
        float i_n = g_gi[gib + 1024];
        size_t fb = ((size_t)s * 64 + bglob) * 1024 + c0 + ej;
        float f_r = g_f[fb];
        float f_i = g_f[fb + 512];

        __syncthreads();

        // Dots: gh[db][r0..r0+2] = h[db][:] . Ws[r][:]
        float a0 = 0.f, a1 = 0.f, a2 = 0.f;
        const float4* hp = (const float4*)&hs[db * HS_PITCH];
        const float4* w0 = (const float4*)&Ws[(r0 + 0) * 512];
        const float4* w1 = (const float4*)&Ws[(r0 + 1) * 512];
        const float4* w2 = (const float4*)&Ws[(r0 + 2) * 512];
#pragma unroll 8
        for (int k = 0; k < 128; k++) {
            float4 h4 = hp[k];
            float4 x0 = w0[k];
            a0 += h4.x * x0.x + h4.y * x0.y + h4.z * x0.z + h4.w * x0.w;
            float4 x1 = w1[k];
            a1 += h4.x * x1.x + h4.y * x1.y + h4.z * x1.z + h4.w * x1.w;
            float4 x2 = w2[k];
            a2 += h4.x * x2.x + h4.y * x2.y + h4.z * x2.z + h4.w * x2.w;
        }
        ghs[(r0 + 0) * 16 + db] = a0;
        ghs[(r0 + 1) * 16 + db] = a1;
        ghs[(r0 + 2) * 16 + db] = a2;
        __syncthreads();

        // Gate epilogue for (eb, ej)
        float h_r = ghs[(ej)      * 16 + eb] + bs[ej];
        float h_i = ghs[(16 + ej) * 16 + eb] + bs[16 + ej];
        float h_n = ghs[(32 + ej) * 16 + eb] + bs[32 + ej];
        float rgate = 1.f / (1.f + expf(-(i_r + h_r + f_r)));
        float igate = 1.f / (1.f + expf(-(i_i + h_i + f_i)));
        float ngate = tanhf(i_n + rgate * h_n);
        float hprev = hs[eb * HS_PITCH + c0 + ej];
        float hy = ngate + igate * (hprev - ngate);

        g_h[(s + 1) & 1][(size_t)(b0 + eb) * 512 + c0 + ej] = hy;
        out[((size_t)bglob * 512 + s) * 512 + c0 + ej] = hy;
        if (s == 511)
            out[(size_t)64 * 512 * 512 + (size_t)bglob * 512 + c0 + ej] = hy;

        // Group-local barrier (32 CTAs sharing this batch group)
        __threadfence();
        __syncthreads();
        if (t == 0) {
            atomicAdd(&g_bar[gid], 1u);
            unsigned target = (unsigned)(s + 1) * 32u;
            while (*((volatile unsigned*)&g_bar[gid]) < target) { }
            __threadfence();
        }
        __syncthreads();
    }
}

// ---------------------------------------------------------------------------
// Launch
// ---------------------------------------------------------------------------
extern "C" void kernel_launch(void* const* d_in, const int* in_sizes, int n_in,
                              void* d_out, int out_size) {
    const float* input = (const float*)d_in[0];   // [B,S,D]
    const float* aux   = (const float*)d_in[1];   // [2,B,S,D]
    const float* hx    = (const float*)d_in[2];   // [B,H]
    const float* w_ih  = (const float*)d_in[3];   // [3H,D]
    const float* w_fh  = (const float*)d_in[4];   // [2,2H,D]
    const float* b_ih  = (const float*)d_in[5];   // [3H]
    const float* b_fh  = (const float*)d_in[6];   // [2,2H]
    const float* w_hh  = (const float*)d_in[7];   // [3H,H]
    const float* b_hh  = (const float*)d_in[8];   // [3H]
    float* out = (float*)d_out;

    cudaFuncSetAttribute(scan_kernel,
                         cudaFuncAttributeMaxDynamicSharedMemorySize,
                         SCAN_SMEM_BYTES);

    init_bar_kernel<<<1, 32>>>();
    gemm_gi_kernel<<<dim3(256, 12), 256>>>(input, w_ih, b_ih);
    gemm_f_kernel<<<dim3(256, 8), 256>>>(aux, w_fh, b_fh);
    scan_kernel<<<128, 256, SCAN_SMEM_BYTES>>>(hx, w_hh, b_hh, out);
}

// round 4
// speedup vs baseline: 1.2782x; 1.2782x over previous
#include <cuda_runtime.h>
#include <cuda_bf16.h>
#include <math.h>
#include <stdint.h>

// Problem sizes (fixed)
#define BB 64     // batch
#define SS 512    // seq len
#define DD 512    // input dim
#define HH 512    // hidden

// ---------------------------------------------------------------------------
// Device scratch (allocation-free rule: device globals only)
// ---------------------------------------------------------------------------
__device__ float g_gi[(size_t)SS * BB * 3 * HH];   // [s][b][3H]
__device__ float g_f [(size_t)SS * BB * 2 * HH];   // [s][b][2H]
__device__ float g_h [2][BB * HH];                 // h ping-pong
__device__ unsigned g_bar[4];                      // per-batch-group barrier

__global__ void init_bar_kernel() {
    if (threadIdx.x < 4) g_bar[threadIdx.x] = 0u;
}

// ---------------------------------------------------------------------------
// mma.sync helpers (sm_80+ vocabulary — works under compute_103 PTX)
// ---------------------------------------------------------------------------
__device__ __forceinline__ uint32_t smem_to_u32(const void* p) {
    uint32_t a;
    asm("{ .reg .u64 t; cvta.to.shared.u64 t, %1; cvt.u32.u64 %0, t; }"
        : "=r"(a) : "l"(p));
    return a;
}

#define LDMATRIX_X4(r, addr) \
    asm volatile("ldmatrix.sync.aligned.m8n8.x4.shared.b16 {%0,%1,%2,%3}, [%4];" \
        : "=r"((r)[0]), "=r"((r)[1]), "=r"((r)[2]), "=r"((r)[3]) : "r"(addr))

#define MMA_BF16(d, a, b0, b1) \
    asm volatile("mma.sync.aligned.m16n8k16.row.col.f32.bf16.bf16.f32 " \
        "{%0,%1,%2,%3}, {%4,%5,%6,%7}, {%8,%9}, {%0,%1,%2,%3};" \
        : "+f"((d)[0]), "+f"((d)[1]), "+f"((d)[2]), "+f"((d)[3]) \
        : "r"((a)[0]), "r"((a)[1]), "r"((a)[2]), "r"((a)[3]), \
          "r"(b0), "r"(b1))

// ---------------------------------------------------------------------------
// GEMM tiling: CTA 128(M) x 128(N), BK=32, 512 threads (16 warps, 4x4 warp
// grid, warp tile 32x32). Smem: double-buffered (Ah, Al, Bh, Bl) tiles,
// each 128 rows x 32 bf16, pitch 40 bf16 (80 B) for conflict-free ldmatrix.
// ---------------------------------------------------------------------------
#define GP 40                              // smem pitch in bf16 elements
#define G_TILE_B (128 * GP * 2)            // 10240 bytes per tile
#define OFF_AH(buf) ((buf) * 4 * G_TILE_B + 0 * G_TILE_B)
#define OFF_AL(buf) ((buf) * 4 * G_TILE_B + 1 * G_TILE_B)
#define OFF_BH(buf) ((buf) * 4 * G_TILE_B + 2 * G_TILE_B)
#define OFF_BL(buf) ((buf) * 4 * G_TILE_B + 3 * G_TILE_B)
#define GEMM_SMEM_BYTES (8 * G_TILE_B)     // 81920

__device__ __forceinline__ uint32_t pack_bf16(float a, float b) {
    return ((uint32_t)__bfloat16_as_ushort(__float2bfloat16_rn(b)) << 16) |
           (uint32_t)__bfloat16_as_ushort(__float2bfloat16_rn(a));
}

// Load 2 float4 per thread from a [128 x 32] fp32 chunk (row stride 512).
__device__ __forceinline__ void ldg_chunk(const float* __restrict__ src,
                                          float4 v[2], int t) {
#pragma unroll
    for (int i = 0; i < 2; i++) {
        int idx = t + 512 * i;             // 0..1023
        int row = idx >> 3;
        int kq  = idx & 7;
        v[i] = *(const float4*)(src + (size_t)row * 512 + kq * 4);
    }
}

// Convert held float4s to bf16 hi/lo and store into swizzle-free pitched smem.
__device__ __forceinline__ void sts_chunk(char* smem, int hi_off, int lo_off,
                                          const float4 v[2], int t) {
#pragma unroll
    for (int i = 0; i < 2; i++) {
        int idx = t + 512 * i;
        int row = idx >> 3;
        int kq  = idx & 7;
        float4 x = v[i];
        float hx = __bfloat162float(__float2bfloat16_rn(x.x));
        float hy = __bfloat162float(__float2bfloat16_rn(x.y));
        float hz = __bfloat162float(__float2bfloat16_rn(x.z));
        float hw = __bfloat162float(__float2bfloat16_rn(x.w));
        uint2 hi = make_uint2(pack_bf16(x.x, x.y), pack_bf16(x.z, x.w));
        uint2 lo = make_uint2(pack_bf16(x.x - hx, x.y - hy),
                              pack_bf16(x.z - hz, x.w - hw));
        uint32_t boff = (uint32_t)(row * GP + kq * 4) * 2;
        *(uint2*)(smem + hi_off + boff) = hi;
        *(uint2*)(smem + lo_off + boff) = lo;
    }
}

// One k16 step of the warp-tile compute: 8 ldmatrix.x4 + 24 mma.
__device__ __forceinline__ void warp_k16(uint32_t sb, int buf, int ks,
                                         int wm, int wn, int lane,
                                         float acc[2][4][4]) {
    const int lr = lane & 7;
    const int lg = lane >> 3;
    // A fragments (hi & lo) for 2 m16 tiles
    uint32_t ah[2][4], al[2][4];
#pragma unroll
    for (int mt = 0; mt < 2; mt++) {
        int arow = wm * 32 + mt * 16 + lr + (lg & 1) * 8;
        int acol = ks * 16 + (lg >> 1) * 8;
        uint32_t boff = (uint32_t)(arow * GP + acol) * 2;
        LDMATRIX_X4(ah[mt], sb + OFF_AH(buf) + boff);
        LDMATRIX_X4(al[mt], sb + OFF_AL(buf) + boff);
    }
    // B fragments (hi & lo) for 2 n16 pairs (4 n8 tiles)
    uint32_t bh[2][4], bl[2][4];
#pragma unroll
    for (int np = 0; np < 2; np++) {
        int brow = wn * 32 + np * 16 + lr + (lg >> 1) * 8;
        int bcol = ks * 16 + (lg & 1) * 8;
        uint32_t boff = (uint32_t)(brow * GP + bcol) * 2;
        LDMATRIX_X4(bh[np], sb + OFF_BH(buf) + boff);
        LDMATRIX_X4(bl[np], sb + OFF_BL(buf) + boff);
    }
    // 3-pass split MMA: hi*hi + hi*lo + lo*hi
#pragma unroll
    for (int mt = 0; mt < 2; mt++)
#pragma unroll
        for (int np = 0; np < 2; np++)
#pragma unroll
            for (int sub = 0; sub < 2; sub++) {
                int nj = np * 2 + sub;
                MMA_BF16(acc[mt][nj], ah[mt], bh[np][2 * sub], bh[np][2 * sub + 1]);
                MMA_BF16(acc[mt][nj], ah[mt], bl[np][2 * sub], bl[np][2 * sub + 1]);
                MMA_BF16(acc[mt][nj], al[mt], bh[np][2 * sub], bh[np][2 * sub + 1]);
            }
}

// ---------------------------------------------------------------------------
// GEMM 1: gi[s][b][n] = input[b][s][:] . W_ih[n][:] + bias_ih[n]
// M = 32768 (m = b*512 + s), N = 1536, K = 512
// ---------------------------------------------------------------------------
__global__ __launch_bounds__(512, 1) void gemm_gi_mma(
    const float* __restrict__ A, const float* __restrict__ W,
    const float* __restrict__ bias)
{
    extern __shared__ char smem[];
    uint32_t sb = smem_to_u32(smem);
    const int t = threadIdx.x;
    const int wid = t >> 5;
    const int lane = t & 31;
    const int wm = wid & 3;
    const int wn = wid >> 2;
    const int m0 = blockIdx.x * 128;
    const int n0 = blockIdx.y * 128;

    float acc[2][4][4];
#pragma unroll
    for (int i = 0; i < 2; i++)
#pragma unroll
        for (int j = 0; j < 4; j++)
#pragma unroll
            for (int k = 0; k < 4; k++) acc[i][j][k] = 0.f;

    const float* Abase = A + (size_t)m0 * 512;
    const float* Wbase = W + (size_t)n0 * 512;

    float4 av[2], bv[2];
    ldg_chunk(Abase, av, t);
    ldg_chunk(Wbase, bv, t);
    sts_chunk(smem, OFF_AH(0), OFF_AL(0), av, t);
    sts_chunk(smem, OFF_BH(0), OFF_BL(0), bv, t);
    __syncthreads();

    const int NC = 16;  // 512 / 32
    for (int c = 0; c < NC; c++) {
        int buf = c & 1;
        if (c + 1 < NC) {
            ldg_chunk(Abase + (c + 1) * 32, av, t);
            ldg_chunk(Wbase + (c + 1) * 32, bv, t);
        }
        warp_k16(sb, buf, 0, wm, wn, lane, acc);
        warp_k16(sb, buf, 1, wm, wn, lane, acc);
        if (c + 1 < NC) {
            __syncthreads();
            sts_chunk(smem, OFF_AH(buf ^ 1), OFF_AL(buf ^ 1), av, t);
            sts_chunk(smem, OFF_BH(buf ^ 1), OFF_BL(buf ^ 1), bv, t);
            __syncthreads();
        }
    }

    // Epilogue: C[m][n] + bias -> g_gi[s][b][n] with m = b*512 + s
    const int qrow = lane >> 2;
    const int qcol = (lane & 3) * 2;
#pragma unroll
    for (int mt = 0; mt < 2; mt++)
#pragma unroll
        for (int half = 0; half < 2; half++) {
            int m = m0 + wm * 32 + mt * 16 + qrow + half * 8;
            int b = m >> 9;
            int s = m & 511;
            float* crow = &g_gi[((size_t)s * 64 + b) * 1536 + n0 + wn * 32];
#pragma unroll
            for (int nj = 0; nj < 4; nj++) {
                int n = nj * 8 + qcol;
                float2 bvv = *(const float2*)&bias[n0 + wn * 32 + n];
                float2 o;
                o.x = acc[mt][nj][half * 2 + 0] + bvv.x;
                o.y = acc[mt][nj][half * 2 + 1] + bvv.y;
                *(float2*)&crow[n] = o;
            }
        }
}

// ---------------------------------------------------------------------------
// GEMM 2: f[s][b][n] = 0.5*sum_a(aux[a][b][s][:] . W_fh[a][n][:])
//                    + 0.5*(bias_fh[0][n] + bias_fh[1][n])
// N = 1024; K accumulated over 2 aux segments of 512.
// ---------------------------------------------------------------------------
__global__ __launch_bounds__(512, 1) void gemm_f_mma(
    const float* __restrict__ Aux, const float* __restrict__ Wf,
    const float* __restrict__ bf)
{
    extern __shared__ char smem[];
    uint32_t sb = smem_to_u32(smem);
    const int t = threadIdx.x;
    const int wid = t >> 5;
    const int lane = t & 31;
    const int wm = wid & 3;
    const int wn = wid >> 2;
    const int m0 = blockIdx.x * 128;
    const int n0 = blockIdx.y * 128;

    float acc[2][4][4];
#pragma unroll
    for (int i = 0; i < 2; i++)
#pragma unroll
        for (int j = 0; j < 4; j++)
#pragma unroll
            for (int k = 0; k < 4; k++) acc[i][j][k] = 0.f;

    float4 av[2], bv[2];
    ldg_chunk(Aux + (size_t)m0 * 512, av, t);
    ldg_chunk(Wf + (size_t)n0 * 512, bv, t);
    sts_chunk(smem, OFF_AH(0), OFF_AL(0), av, t);
    sts_chunk(smem, OFF_BH(0), OFF_BL(0), bv, t);
    __syncthreads();

    const int NC = 32;  // 2 segments x 16 chunks
    for (int c = 0; c < NC; c++) {
        int buf = c & 1;
        if (c + 1 < NC) {
            int cn = c + 1;
            int seg = cn >> 4, kk = cn & 15;
            const float* An = Aux + (size_t)seg * 32768 * 512 + (size_t)m0 * 512 + kk * 32;
            const float* Wn = Wf + (size_t)seg * 1024 * 512 + (size_t)n0 * 512 + kk * 32;
            ldg_chunk(An, av, t);
            ldg_chunk(Wn, bv, t);
        }
        warp_k16(sb, buf, 0, wm, wn, lane, acc);
        warp_k16(sb, buf, 1, wm, wn, lane, acc);
        if (c + 1 < NC) {
            __syncthreads();
            sts_chunk(smem, OFF_AH(buf ^ 1), OFF_AL(buf ^ 1), av, t);
            sts_chunk(smem, OFF_BH(buf ^ 1), OFF_BL(buf ^ 1), bv, t);
            __syncthreads();
        }
    }

    const int qrow = lane >> 2;
    const int qcol = (lane & 3) * 2;
#pragma unroll
    for (int mt = 0; mt < 2; mt++)
#pragma unroll
        for (int half = 0; half < 2; half++) {
            int m = m0 + wm * 32 + mt * 16 + qrow + half * 8;
            int b = m >> 9;
            int s = m & 511;
            float* crow = &g_f[((size_t)s * 64 + b) * 1024 + n0 + wn * 32];
#pragma unroll
            for (int nj = 0; nj < 4; nj++) {
                int n = nj * 8 + qcol;
                int ng = n0 + wn * 32 + n;
                float2 b0 = *(const float2*)&bf[ng];
                float2 b1 = *(const float2*)&bf[1024 + ng];
                float2 o;
                o.x = 0.5f * acc[mt][nj][half * 2 + 0] + 0.5f * (b0.x + b1.x);
                o.y = 0.5f * acc[mt][nj][half * 2 + 1] + 0.5f * (b0.y + b1.y);
                *(float2*)&crow[n] = o;
            }
        }
}

// ---------------------------------------------------------------------------
// Persistent recurrent scan (unchanged from the passing round-1 kernel).
// ---------------------------------------------------------------------------
#define HS_PITCH 516
#define SCAN_SMEM_FLOATS (48 * 512 + 16 * HS_PITCH + 48 * 16 + 48)
#define SCAN_SMEM_BYTES  (SCAN_SMEM_FLOATS * 4)

__global__ __launch_bounds__(256, 1) void scan_kernel(
    const float* __restrict__ hx, const float* __restrict__ Whh,
    const float* __restrict__ bias_hh, float* __restrict__ out)
{
    extern __shared__ float smemf[];
    float* Ws  = smemf;                    // [48][512]
    float* hs  = Ws + 48 * 512;            // [16][HS_PITCH]
    float* ghs = hs + 16 * HS_PITCH;       // [48][16]
    float* bs  = ghs + 48 * 16;            // [48]

    const int t   = threadIdx.x;
    const int gid = blockIdx.x >> 5;       // batch group 0..3
    const int cid = blockIdx.x & 31;       // column CTA 0..31
    const int b0  = gid * 16;
    const int c0  = cid * 16;

    for (int i = t; i < 48 * 128; i += 256) {
        int r  = i >> 7;
        int c4 = i & 127;
        int gate = r >> 4, j = r & 15;
        int grow = gate * 512 + c0 + j;
        *(float4*)&Ws[r * 512 + c4 * 4] =
            *(const float4*)&Whh[(size_t)grow * 512 + c4 * 4];
    }
    if (t < 48) {
        int gate = t >> 4, j = t & 15;
        bs[t] = bias_hh[gate * 512 + c0 + j];
    }

    const int db = t & 15;
    const int rg = t >> 4;
    const int r0 = rg * 3;
    const int eb = t >> 4;
    const int ej = t & 15;
    const int bglob = b0 + eb;

    for (int s = 0; s < 512; s++) {
        const float* hsrc = (s == 0) ? (hx + (size_t)b0 * 512)
                                     : (g_h[s & 1] + (size_t)b0 * 512);
        for (int i = t; i < 2048; i += 256) {
            int bb = i >> 7;
            int c4 = i & 127;
            *(float4*)&hs[bb * HS_PITCH + c4 * 4] =
                *(const float4*)&hsrc[bb * 512 + c4 * 4];
        }

        size_t gib = ((size_t)s * 64 + bglob) * 1536 + c0 + ej;
        float i_r = g_gi[gib];
        float i_i = g_gi[gib + 512];
        float i_n = g_gi[gib + 1024];
        size_t fb = ((size_t)s * 64 + bglob) * 1024 + c0 + ej;
        float f_r = g_f[fb];
        float f_i = g_f[fb + 512];

        __syncthreads();

        float a0 = 0.f, a1 = 0.f, a2 = 0.f;
        const float4* hp = (const float4*)&hs[db * HS_PITCH];
        const float4* w0 = (const float4*)&Ws[(r0 + 0) * 512];
        const float4* w1 = (const float4*)&Ws[(r0 + 1) * 512];
        const float4* w2 = (const float4*)&Ws[(r0 + 2) * 512];
#pragma unroll 8
        for (int k = 0; k < 128; k++) {
            float4 h4 = hp[k];
            float4 x0 = w0[k];
            a0 += h4.x * x0.x + h4.y * x0.y + h4.z * x0.z + h4.w * x0.w;
            float4 x1 = w1[k];
            a1 += h4.x * x1.x + h4.y * x1.y + h4.z * x1.z + h4.w * x1.w;
            float4 x2 = w2[k];
            a2 += h4.x * x2.x + h4.y * x2.y + h4.z * x2.z + h4.w * x2.w;
        }
        ghs[(r0 + 0) * 16 + db] = a0;
        ghs[(r0 + 1) * 16 + db] = a1;
        ghs[(r0 + 2) * 16 + db] = a2;
        __syncthreads();

        float h_r = ghs[(ej)      * 16 + eb] + bs[ej];
        float h_i = ghs[(16 + ej) * 16 + eb] + bs[16 + ej];
        float h_n = ghs[(32 + ej) * 16 + eb] + bs[32 + ej];
        float rgate = 1.f / (1.f + expf(-(i_r + h_r + f_r)));
        float igate = 1.f / (1.f + expf(-(i_i + h_i + f_i)));
        float ngate = tanhf(i_n + rgate * h_n);
        float hprev = hs[eb * HS_PITCH + c0 + ej];
        float hy = ngate + igate * (hprev - ngate);

        g_h[(s + 1) & 1][(size_t)(b0 + eb) * 512 + c0 + ej] = hy;
        out[((size_t)bglob * 512 + s) * 512 + c0 + ej] = hy;
        if (s == 511)
            out[(size_t)64 * 512 * 512 + (size_t)bglob * 512 + c0 + ej] = hy;

        __threadfence();
        __syncthreads();
        if (t == 0) {
            atomicAdd(&g_bar[gid], 1u);
            unsigned target = (unsigned)(s + 1) * 32u;
            while (*((volatile unsigned*)&g_bar[gid]) < target) { }
            __threadfence();
        }
        __syncthreads();
    }
}

// ---------------------------------------------------------------------------
// Launch
// ---------------------------------------------------------------------------
extern "C" void kernel_launch(void* const* d_in, const int* in_sizes, int n_in,
                              void* d_out, int out_size) {
    const float* input = (const float*)d_in[0];   // [B,S,D]
    const float* aux   = (const float*)d_in[1];   // [2,B,S,D]
    const float* hx    = (const float*)d_in[2];   // [B,H]
    const float* w_ih  = (const float*)d_in[3];   // [3H,D]
    const float* w_fh  = (const float*)d_in[4];   // [2,2H,D]
    const float* b_ih  = (const float*)d_in[5];   // [3H]
    const float* b_fh  = (const float*)d_in[6];   // [2,2H]
    const float* w_hh  = (const float*)d_in[7];   // [3H,H]
    const float* b_hh  = (const float*)d_in[8];   // [3H]
    float* out = (float*)d_out;

    cudaFuncSetAttribute(gemm_gi_mma,
                         cudaFuncAttributeMaxDynamicSharedMemorySize,
                         GEMM_SMEM_BYTES);
    cudaFuncSetAttribute(gemm_f_mma,
                         cudaFuncAttributeMaxDynamicSharedMemorySize,
                         GEMM_SMEM_BYTES);
    cudaFuncSetAttribute(scan_kernel,
                         cudaFuncAttributeMaxDynamicSharedMemorySize,
                         SCAN_SMEM_BYTES);

    init_bar_kernel<<<1, 32>>>();
    gemm_gi_mma<<<dim3(256, 12), 512, GEMM_SMEM_BYTES>>>(input, w_ih, b_ih);
    gemm_f_mma<<<dim3(256, 8), 512, GEMM_SMEM_BYTES>>>(aux, w_fh, b_fh);
    scan_kernel<<<128, 256, SCAN_SMEM_BYTES>>>(hx, w_hh, b_hh, out);
}

// round 5
// speedup vs baseline: 2.2069x; 1.7266x over previous
#include <cuda_runtime.h>
#include <cuda_bf16.h>
#include <math.h>
#include <stdint.h>

// Problem sizes (fixed)
#define BB 64     // batch
#define SS 512    // seq len
#define DD 512    // input dim
#define HH 512    // hidden

// ---------------------------------------------------------------------------
// Device scratch (allocation-free rule: device globals only)
// ---------------------------------------------------------------------------
__device__ float g_gi[(size_t)SS * BB * 3 * HH];   // [s][b][3H]
__device__ float g_f [(size_t)SS * BB * 2 * HH];   // [s][b][2H]
__device__ float g_h [2][BB * HH];                 // h ping-pong
__device__ unsigned g_bar[4];                      // per-batch-group barrier

__global__ void init_bar_kernel() {
    if (threadIdx.x < 4) g_bar[threadIdx.x] = 0u;
}

// ---------------------------------------------------------------------------
// mma.sync helpers (sm_80+ vocabulary — works under compute_103 PTX)
// ---------------------------------------------------------------------------
__device__ __forceinline__ uint32_t smem_to_u32(const void* p) {
    uint32_t a;
    asm("{ .reg .u64 t; cvta.to.shared.u64 t, %1; cvt.u32.u64 %0, t; }"
        : "=r"(a) : "l"(p));
    return a;
}

#define LDMATRIX_X4(r, addr) \
    asm volatile("ldmatrix.sync.aligned.m8n8.x4.shared.b16 {%0,%1,%2,%3}, [%4];" \
        : "=r"((r)[0]), "=r"((r)[1]), "=r"((r)[2]), "=r"((r)[3]) : "r"(addr))

#define MMA_BF16(d, a, b0, b1) \
    asm volatile("mma.sync.aligned.m16n8k16.row.col.f32.bf16.bf16.f32 " \
        "{%0,%1,%2,%3}, {%4,%5,%6,%7}, {%8,%9}, {%0,%1,%2,%3};" \
        : "+f"((d)[0]), "+f"((d)[1]), "+f"((d)[2]), "+f"((d)[3]) \
        : "r"((a)[0]), "r"((a)[1]), "r"((a)[2]), "r"((a)[3]), \
          "r"(b0), "r"(b1))

__device__ __forceinline__ uint32_t pack_bf16(float a, float b) {
    return ((uint32_t)__bfloat16_as_ushort(__float2bfloat16_rn(b)) << 16) |
           (uint32_t)__bfloat16_as_ushort(__float2bfloat16_rn(a));
}

// ---------------------------------------------------------------------------
// Precompute GEMMs (unchanged from passing round-4 kernel).
// CTA 128x128, BK=32, 512 threads (16 warps, 4x4), bf16 hi/lo 3-pass split.
// ---------------------------------------------------------------------------
#define GP 40                              // smem pitch in bf16 elements
#define G_TILE_B (128 * GP * 2)            // 10240 bytes per tile
#define OFF_AH(buf) ((buf) * 4 * G_TILE_B + 0 * G_TILE_B)
#define OFF_AL(buf) ((buf) * 4 * G_TILE_B + 1 * G_TILE_B)
#define OFF_BH(buf) ((buf) * 4 * G_TILE_B + 2 * G_TILE_B)
#define OFF_BL(buf) ((buf) * 4 * G_TILE_B + 3 * G_TILE_B)
#define GEMM_SMEM_BYTES (8 * G_TILE_B)     // 81920

__device__ __forceinline__ void ldg_chunk(const float* __restrict__ src,
                                          float4 v[2], int t) {
#pragma unroll
    for (int i = 0; i < 2; i++) {
        int idx = t + 512 * i;
        int row = idx >> 3;
        int kq  = idx & 7;
        v[i] = *(const float4*)(src + (size_t)row * 512 + kq * 4);
    }
}

__device__ __forceinline__ void sts_chunk(char* smem, int hi_off, int lo_off,
                                          const float4 v[2], int t) {
#pragma unroll
    for (int i = 0; i < 2; i++) {
        int idx = t + 512 * i;
        int row = idx >> 3;
        int kq  = idx & 7;
        float4 x = v[i];
        float hx = __bfloat162float(__float2bfloat16_rn(x.x));
        float hy = __bfloat162float(__float2bfloat16_rn(x.y));
        float hz = __bfloat162float(__float2bfloat16_rn(x.z));
        float hw = __bfloat162float(__float2bfloat16_rn(x.w));
        uint2 hi = make_uint2(pack_bf16(x.x, x.y), pack_bf16(x.z, x.w));
        uint2 lo = make_uint2(pack_bf16(x.x - hx, x.y - hy),
                              pack_bf16(x.z - hz, x.w - hw));
        uint32_t boff = (uint32_t)(row * GP + kq * 4) * 2;
        *(uint2*)(smem + hi_off + boff) = hi;
        *(uint2*)(smem + lo_off + boff) = lo;
    }
}

__device__ __forceinline__ void warp_k16(uint32_t sb, int buf, int ks,
                                         int wm, int wn, int lane,
                                         float acc[2][4][4]) {
    const int lr = lane & 7;
    const int lg = lane >> 3;
    uint32_t ah[2][4], al[2][4];
#pragma unroll
    for (int mt = 0; mt < 2; mt++) {
        int arow = wm * 32 + mt * 16 + lr + (lg & 1) * 8;
        int acol = ks * 16 + (lg >> 1) * 8;
        uint32_t boff = (uint32_t)(arow * GP + acol) * 2;
        LDMATRIX_X4(ah[mt], sb + OFF_AH(buf) + boff);
        LDMATRIX_X4(al[mt], sb + OFF_AL(buf) + boff);
    }
    uint32_t bh[2][4], bl[2][4];
#pragma unroll
    for (int np = 0; np < 2; np++) {
        int brow = wn * 32 + np * 16 + lr + (lg >> 1) * 8;
        int bcol = ks * 16 + (lg & 1) * 8;
        uint32_t boff = (uint32_t)(brow * GP + bcol) * 2;
        LDMATRIX_X4(bh[np], sb + OFF_BH(buf) + boff);
        LDMATRIX_X4(bl[np], sb + OFF_BL(buf) + boff);
    }
#pragma unroll
    for (int mt = 0; mt < 2; mt++)
#pragma unroll
        for (int np = 0; np < 2; np++)
#pragma unroll
            for (int sub = 0; sub < 2; sub++) {
                int nj = np * 2 + sub;
                MMA_BF16(acc[mt][nj], ah[mt], bh[np][2 * sub], bh[np][2 * sub + 1]);
                MMA_BF16(acc[mt][nj], ah[mt], bl[np][2 * sub], bl[np][2 * sub + 1]);
                MMA_BF16(acc[mt][nj], al[mt], bh[np][2 * sub], bh[np][2 * sub + 1]);
            }
}

__global__ __launch_bounds__(512, 1) void gemm_gi_mma(
    const float* __restrict__ A, const float* __restrict__ W,
    const float* __restrict__ bias)
{
    extern __shared__ char smem[];
    uint32_t sb = smem_to_u32(smem);
    const int t = threadIdx.x;
    const int wid = t >> 5;
    const int lane = t & 31;
    const int wm = wid & 3;
    const int wn = wid >> 2;
    const int m0 = blockIdx.x * 128;
    const int n0 = blockIdx.y * 128;

    float acc[2][4][4];
#pragma unroll
    for (int i = 0; i < 2; i++)
#pragma unroll
        for (int j = 0; j < 4; j++)
#pragma unroll
            for (int k = 0; k < 4; k++) acc[i][j][k] = 0.f;

    const float* Abase = A + (size_t)m0 * 512;
    const float* Wbase = W + (size_t)n0 * 512;

    float4 av[2], bv[2];
    ldg_chunk(Abase, av, t);
    ldg_chunk(Wbase, bv, t);
    sts_chunk(smem, OFF_AH(0), OFF_AL(0), av, t);
    sts_chunk(smem, OFF_BH(0), OFF_BL(0), bv, t);
    __syncthreads();

    const int NC = 16;
    for (int c = 0; c < NC; c++) {
        int buf = c & 1;
        if (c + 1 < NC) {
            ldg_chunk(Abase + (c + 1) * 32, av, t);
            ldg_chunk(Wbase + (c + 1) * 32, bv, t);
        }
        warp_k16(sb, buf, 0, wm, wn, lane, acc);
        warp_k16(sb, buf, 1, wm, wn, lane, acc);
        if (c + 1 < NC) {
            __syncthreads();
            sts_chunk(smem, OFF_AH(buf ^ 1), OFF_AL(buf ^ 1), av, t);
            sts_chunk(smem, OFF_BH(buf ^ 1), OFF_BL(buf ^ 1), bv, t);
            __syncthreads();
        }
    }

    const int qrow = lane >> 2;
    const int qcol = (lane & 3) * 2;
#pragma unroll
    for (int mt = 0; mt < 2; mt++)
#pragma unroll
        for (int half = 0; half < 2; half++) {
            int m = m0 + wm * 32 + mt * 16 + qrow + half * 8;
            int b = m >> 9;
            int s = m & 511;
            float* crow = &g_gi[((size_t)s * 64 + b) * 1536 + n0 + wn * 32];
#pragma unroll
            for (int nj = 0; nj < 4; nj++) {
                int n = nj * 8 + qcol;
                float2 bvv = *(const float2*)&bias[n0 + wn * 32 + n];
                float2 o;
                o.x = acc[mt][nj][half * 2 + 0] + bvv.x;
                o.y = acc[mt][nj][half * 2 + 1] + bvv.y;
                *(float2*)&crow[n] = o;
            }
        }
}

__global__ __launch_bounds__(512, 1) void gemm_f_mma(
    const float* __restrict__ Aux, const float* __restrict__ Wf,
    const float* __restrict__ bf)
{
    extern __shared__ char smem[];
    uint32_t sb = smem_to_u32(smem);
    const int t = threadIdx.x;
    const int wid = t >> 5;
    const int lane = t & 31;
    const int wm = wid & 3;
    const int wn = wid >> 2;
    const int m0 = blockIdx.x * 128;
    const int n0 = blockIdx.y * 128;

    float acc[2][4][4];
#pragma unroll
    for (int i = 0; i < 2; i++)
#pragma unroll
        for (int j = 0; j < 4; j++)
#pragma unroll
            for (int k = 0; k < 4; k++) acc[i][j][k] = 0.f;

    float4 av[2], bv[2];
    ldg_chunk(Aux + (size_t)m0 * 512, av, t);
    ldg_chunk(Wf + (size_t)n0 * 512, bv, t);
    sts_chunk(smem, OFF_AH(0), OFF_AL(0), av, t);
    sts_chunk(smem, OFF_BH(0), OFF_BL(0), bv, t);
    __syncthreads();

    const int NC = 32;
    for (int c = 0; c < NC; c++) {
        int buf = c & 1;
        if (c + 1 < NC) {
            int cn = c + 1;
            int seg = cn >> 4, kk = cn & 15;
            const float* An = Aux + (size_t)seg * 32768 * 512 + (size_t)m0 * 512 + kk * 32;
            const float* Wn = Wf + (size_t)seg * 1024 * 512 + (size_t)n0 * 512 + kk * 32;
            ldg_chunk(An, av, t);
            ldg_chunk(Wn, bv, t);
        }
        warp_k16(sb, buf, 0, wm, wn, lane, acc);
        warp_k16(sb, buf, 1, wm, wn, lane, acc);
        if (c + 1 < NC) {
            __syncthreads();
            sts_chunk(smem, OFF_AH(buf ^ 1), OFF_AL(buf ^ 1), av, t);
            sts_chunk(smem, OFF_BH(buf ^ 1), OFF_BL(buf ^ 1), bv, t);
            __syncthreads();
        }
    }

    const int qrow = lane >> 2;
    const int qcol = (lane & 3) * 2;
#pragma unroll
    for (int mt = 0; mt < 2; mt++)
#pragma unroll
        for (int half = 0; half < 2; half++) {
            int m = m0 + wm * 32 + mt * 16 + qrow + half * 8;
            int b = m >> 9;
            int s = m & 511;
            float* crow = &g_f[((size_t)s * 64 + b) * 1024 + n0 + wn * 32];
#pragma unroll
            for (int nj = 0; nj < 4; nj++) {
                int n = nj * 8 + qcol;
                int ng = n0 + wn * 32 + n;
                float2 b0 = *(const float2*)&bf[ng];
                float2 b1 = *(const float2*)&bf[1024 + ng];
                float2 o;
                o.x = 0.5f * acc[mt][nj][half * 2 + 0] + 0.5f * (b0.x + b1.x);
                o.y = 0.5f * acc[mt][nj][half * 2 + 1] + 0.5f * (b0.y + b1.y);
                *(float2*)&crow[n] = o;
            }
        }
}

// ---------------------------------------------------------------------------
// Persistent recurrent scan — MMA version.
// Grid 128 = 4 batch-groups (16 b) x 32 column-CTAs (16 hy cols = 48 W rows).
// W_hh slice -> bf16 hi/lo fragments in REGISTERS (loaded once).
// Per step: h (16x512 fp32) -> bf16 hi/lo smem; 8 warps split K (64 each);
// 72 mma.sync per warp (3-pass hi/lo split); 8-way smem reduction; gates;
// red.release/ld.acquire global barrier over the 32-CTA group.
// ---------------------------------------------------------------------------
#define SPITCH 520                       // bf16 pitch (1040 B: 16B/row rotation)
#define S_OFF_WH  0                      // 48 x 520 bf16 = 49920 B
#define S_OFF_WL  49920                  // 49920 B
#define S_OFF_HH  99840                  // 16 x 520 bf16 = 16640 B
#define S_OFF_HL  116480                 // 16640 B
#define S_OFF_RED 133120                 // 8 x 768 fp32 = 24576 B
#define S_OFF_GHS 157696                 // 768 fp32 = 3072 B
#define S_OFF_BS  160768                 // 48 fp32 = 192 B
#define SCAN_SMEM_BYTES 160960

__global__ __launch_bounds__(256, 1) void scan_kernel(
    const float* __restrict__ hx, const float* __restrict__ Whh,
    const float* __restrict__ bias_hh, float* __restrict__ out)
{
    extern __shared__ char smem[];
    uint32_t sb = smem_to_u32(smem);
    float* redf = (float*)(smem + S_OFF_RED);
    float* ghs  = (float*)(smem + S_OFF_GHS);
    float* bs   = (float*)(smem + S_OFF_BS);

    const int t    = threadIdx.x;
    const int w    = t >> 5;               // warp 0..7 (K-slice 64 each)
    const int lane = t & 31;
    const int lr   = lane & 7;
    const int lg   = lane >> 3;
    const int gid  = blockIdx.x >> 5;      // batch group 0..3
    const int cid  = blockIdx.x & 31;      // column CTA 0..31
    const int b0   = gid * 16;
    const int c0   = cid * 16;

    // --- Stage W_hh slice (48 rows x 512) as bf16 hi/lo into smem ---
    for (int i = t; i < 48 * 128; i += 256) {
        int r = i >> 7;                    // 0..47
        int q = i & 127;                   // float4 index
        int gate = r >> 4, j = r & 15;
        float4 v = *(const float4*)&Whh[(size_t)(gate * 512 + c0 + j) * 512 + q * 4];
        float hx0 = __bfloat162float(__float2bfloat16_rn(v.x));
        float hy0 = __bfloat162float(__float2bfloat16_rn(v.y));
        float hz0 = __bfloat162float(__float2bfloat16_rn(v.z));
        float hw0 = __bfloat162float(__float2bfloat16_rn(v.w));
        uint2 hi = make_uint2(pack_bf16(v.x, v.y), pack_bf16(v.z, v.w));
        uint2 lo = make_uint2(pack_bf16(v.x - hx0, v.y - hy0),
                              pack_bf16(v.z - hz0, v.w - hw0));
        uint32_t boff = (uint32_t)(r * SPITCH + q * 4) * 2;
        *(uint2*)(smem + S_OFF_WH + boff) = hi;
        *(uint2*)(smem + S_OFF_WL + boff) = lo;
    }
    if (t < 48) {
        int gate = t >> 4, j = t & 15;
        bs[t] = bias_hh[gate * 512 + c0 + j];
    }
    __syncthreads();

    // --- Preload W fragments into registers (per warp: 3 n16-groups x 4 k16) ---
    uint32_t bfh[3][4][4], bfl[3][4][4];
#pragma unroll
    for (int np = 0; np < 3; np++)
#pragma unroll
        for (int ks = 0; ks < 4; ks++) {
            int brow = np * 16 + lr + (lg >> 1) * 8;
            int bcol = w * 64 + ks * 16 + (lg & 1) * 8;
            uint32_t boff = (uint32_t)(brow * SPITCH + bcol) * 2;
            LDMATRIX_X4(bfh[np][ks], sb + S_OFF_WH + boff);
            LDMATRIX_X4(bfl[np][ks], sb + S_OFF_WL + boff);
        }

    const int eb = t >> 4;                 // epilogue batch 0..15
    const int ej = t & 15;                 // epilogue column 0..15
    const int bglob = b0 + eb;
    const int qrow = lane >> 2;
    const int qcol = (lane & 3) * 2;

    unsigned* barp = &g_bar[gid];

    for (int s = 0; s < 512; s++) {
        const float* hsrc = (s == 0) ? (hx + (size_t)b0 * 512)
                                     : (g_h[s & 1] + (size_t)b0 * 512);
        // --- Convert h (16x512 fp32) to bf16 hi/lo smem ---
#pragma unroll
        for (int i = 0; i < 8; i++) {
            int idx = t + 256 * i;         // 0..2047
            int row = idx >> 7;            // 0..15
            int q   = idx & 127;
            float4 v = *(const float4*)&hsrc[(size_t)row * 512 + q * 4];
            float hx0 = __bfloat162float(__float2bfloat16_rn(v.x));
            float hy0 = __bfloat162float(__float2bfloat16_rn(v.y));
            float hz0 = __bfloat162float(__float2bfloat16_rn(v.z));
            float hw0 = __bfloat162float(__float2bfloat16_rn(v.w));
            uint2 hi = make_uint2(pack_bf16(v.x, v.y), pack_bf16(v.z, v.w));
            uint2 lo = make_uint2(pack_bf16(v.x - hx0, v.y - hy0),
                                  pack_bf16(v.z - hz0, v.w - hw0));
            uint32_t boff = (uint32_t)(row * SPITCH + q * 4) * 2;
            *(uint2*)(smem + S_OFF_HH + boff) = hi;
            *(uint2*)(smem + S_OFF_HL + boff) = lo;
        }

        // --- Prefetch gi / f / hprev (independent of MMA) ---
        size_t gib = ((size_t)s * 64 + bglob) * 1536 + c0 + ej;
        float i_r = g_gi[gib];
        float i_i = g_gi[gib + 512];
        float i_n = g_gi[gib + 1024];
        size_t fb = ((size_t)s * 64 + bglob) * 1024 + c0 + ej;
        float f_r = g_f[fb];
        float f_i = g_f[fb + 512];
        float hprev = hsrc[(size_t)eb * 512 + c0 + ej];

        __syncthreads();   // h bf16 tiles visible

        // --- MMA phase: gh partial over warp's K-slice ---
        float acc[6][4];
#pragma unroll
        for (int nj = 0; nj < 6; nj++)
#pragma unroll
            for (int k = 0; k < 4; k++) acc[nj][k] = 0.f;

#pragma unroll
        for (int ks = 0; ks < 4; ks++) {
            uint32_t ah[4], al[4];
            int arow = lr + (lg & 1) * 8;
            int acol = w * 64 + ks * 16 + (lg >> 1) * 8;
            uint32_t aoff = (uint32_t)(arow * SPITCH + acol) * 2;
            LDMATRIX_X4(ah, sb + S_OFF_HH + aoff);
            LDMATRIX_X4(al, sb + S_OFF_HL + aoff);
#pragma unroll
            for (int np = 0; np < 3; np++)
#pragma unroll
                for (int sub = 0; sub < 2; sub++) {
                    int nj = np * 2 + sub;
                    MMA_BF16(acc[nj], ah, bfh[np][ks][2 * sub], bfh[np][ks][2 * sub + 1]);
                    MMA_BF16(acc[nj], ah, bfl[np][ks][2 * sub], bfl[np][ks][2 * sub + 1]);
                    MMA_BF16(acc[nj], al, bfh[np][ks][2 * sub], bfh[np][ks][2 * sub + 1]);
                }
        }

        // --- Store partials [n48 x m16] per warp ---
        {
            float* red = redf + w * 768;
#pragma unroll
            for (int nj = 0; nj < 6; nj++)
#pragma unroll
                for (int half = 0; half < 2; half++) {
                    int m = qrow + half * 8;
                    int n = nj * 8 + qcol;
                    red[n * 16 + m]       = acc[nj][half * 2 + 0];
                    red[(n + 1) * 16 + m] = acc[nj][half * 2 + 1];
                }
        }
        __syncthreads();

        // --- 8-way reduction -> ghs[n*16+m] ---
#pragma unroll
        for (int j = 0; j < 3; j++) {
            int o = t + 256 * j;
            float acc_r = redf[o];
#pragma unroll
            for (int w2 = 1; w2 < 8; w2++) acc_r += redf[w2 * 768 + o];
            ghs[o] = acc_r;
        }
        __syncthreads();

        // --- Gate epilogue for (eb, ej) ---
        float h_r = ghs[ej * 16 + eb]        + bs[ej];
        float h_i = ghs[(16 + ej) * 16 + eb] + bs[16 + ej];
        float h_n = ghs[(32 + ej) * 16 + eb] + bs[32 + ej];
        float rgate = 1.f / (1.f + expf(-(i_r + h_r + f_r)));
        float igate = 1.f / (1.f + expf(-(i_i + h_i + f_i)));
        float ngate = tanhf(i_n + rgate * h_n);
        float hy = ngate + igate * (hprev - ngate);

        g_h[(s + 1) & 1][(size_t)bglob * 512 + c0 + ej] = hy;
        out[((size_t)bglob * 512 + s) * 512 + c0 + ej] = hy;
        if (s == 511)
            out[(size_t)64 * 512 * 512 + (size_t)bglob * 512 + c0 + ej] = hy;

        // --- Group barrier: release-arrive + acquire-spin ---
        __syncthreads();                   // all threads' hy stores done
        if (t == 0) {
            asm volatile("red.release.gpu.global.add.u32 [%0], %1;"
                         :: "l"(barp), "r"(1u) : "memory");
            unsigned target = (unsigned)(s + 1) * 32u;
            unsigned v;
            do {
                asm volatile("ld.acquire.gpu.global.u32 %0, [%1];"
                             : "=r"(v) : "l"(barp) : "memory");
            } while (v < target);
        }
        __syncthreads();
    }
}

// ---------------------------------------------------------------------------
// Launch
// ---------------------------------------------------------------------------
extern "C" void kernel_launch(void* const* d_in, const int* in_sizes, int n_in,
                              void* d_out, int out_size) {
    const float* input = (const float*)d_in[0];   // [B,S,D]
    const float* aux   = (const float*)d_in[1];   // [2,B,S,D]
    const float* hx    = (const float*)d_in[2];   // [B,H]
    const float* w_ih  = (const float*)d_in[3];   // [3H,D]
    const float* w_fh  = (const float*)d_in[4];   // [2,2H,D]
    const float* b_ih  = (const float*)d_in[5];   // [3H]
    const float* b_fh  = (const float*)d_in[6];   // [2,2H]
    const float* w_hh  = (const float*)d_in[7];   // [3H,H]
    const float* b_hh  = (const float*)d_in[8];   // [3H]
    float* out = (float*)d_out;

    cudaFuncSetAttribute(gemm_gi_mma,
                         cudaFuncAttributeMaxDynamicSharedMemorySize,
                         GEMM_SMEM_BYTES);
    cudaFuncSetAttribute(gemm_f_mma,
                         cudaFuncAttributeMaxDynamicSharedMemorySize,
                         GEMM_SMEM_BYTES);
    cudaFuncSetAttribute(scan_kernel,
                         cudaFuncAttributeMaxDynamicSharedMemorySize,
                         SCAN_SMEM_BYTES);

    init_bar_kernel<<<1, 32>>>();
    gemm_gi_mma<<<dim3(256, 12), 512, GEMM_SMEM_BYTES>>>(input, w_ih, b_ih);
    gemm_f_mma<<<dim3(256, 8), 512, GEMM_SMEM_BYTES>>>(aux, w_fh, b_fh);
    scan_kernel<<<128, 256, SCAN_SMEM_BYTES>>>(hx, w_hh, b_hh, out);
}